// round 1
// baseline (speedup 1.0000x reference)
#include <cuda_runtime.h>
#include <math.h>

#define NW 6

// Precomputed variational-circuit matrix U (row-major, U[row*64+col]), complex float2.
__device__ float2 d_U[64 * 64];

// ---------------- complex helpers ----------------
__device__ __forceinline__ float2 cmul(float2 a, float2 b) {
    return make_float2(a.x * b.x - a.y * b.y, a.x * b.y + a.y * b.x);
}
__device__ __forceinline__ float2 cadd(float2 a, float2 b) {
    return make_float2(a.x + b.x, a.y + b.y);
}
__device__ __forceinline__ float2 cscale(float2 a, float s) {
    return make_float2(a.x * s, a.y * s);
}
__device__ __forceinline__ float2 shflxor(float2 v, int m) {
    v.x = __shfl_xor_sync(0xffffffffu, v.x, m);
    v.y = __shfl_xor_sync(0xffffffffu, v.y, m);
    return v;
}

// ---------------- gate application on warp-held state ----------------
// State: 64 complex amplitudes across a warp; lane holds indices n0=2*lane, n1=2*lane+1.
// Wire w corresponds to bit (5-w) of the amplitude index (wire 0 most significant).

// Diagonal gate diag(d0, d1) on wire w.
__device__ __forceinline__ void apply_diag(float2& s0, float2& s1, int lane, int w,
                                           float2 d0, float2 d1) {
    int bit = 5 - w;
    if (bit == 0) {
        s0 = cmul(s0, d0);
        s1 = cmul(s1, d1);
    } else {
        int mb = (lane >> (bit - 1)) & 1;
        float2 d = mb ? d1 : d0;
        s0 = cmul(s0, d);
        s1 = cmul(s1, d);
    }
}

// General 2x2 complex gate on wire w.
__device__ __forceinline__ void apply1(float2& s0, float2& s1, int lane, int w,
                                       float2 u00, float2 u01, float2 u10, float2 u11) {
    int bit = 5 - w;
    if (bit == 0) {
        float2 t0 = cadd(cmul(u00, s0), cmul(u01, s1));
        float2 t1 = cadd(cmul(u10, s0), cmul(u11, s1));
        s0 = t0; s1 = t1;
    } else {
        int lm = 1 << (bit - 1);
        float2 p0 = shflxor(s0, lm);
        float2 p1 = shflxor(s1, lm);
        int mb = (lane >> (bit - 1)) & 1;
        if (mb == 0) {
            s0 = cadd(cmul(u00, s0), cmul(u01, p0));
            s1 = cadd(cmul(u00, s1), cmul(u01, p1));
        } else {
            s0 = cadd(cmul(u10, p0), cmul(u11, s0));
            s1 = cadd(cmul(u10, p1), cmul(u11, s1));
        }
    }
}

// Beamsplitter element update. na = occupation of wire w, nb = wire w+1.
// |00>->|00>; |11>->cos(2th)|11>; a01' = c*a01 + e^{i ph} s*a10 ; a10' = -e^{-i ph} s*a01 + c*a10
__device__ __forceinline__ float2 bsu(float2 s, float2 p, int na, int nb,
                                      float c, float sn, float c2, float ex, float ey) {
    if (na == nb) return na ? cscale(s, c2) : s;
    if (na == 0) { // this amp is |01>, partner |10>
        return make_float2(c * s.x + sn * (ex * p.x - ey * p.y),
                           c * s.y + sn * (ex * p.y + ey * p.x));
    } else {       // this amp is |10>, partner |01>
        return make_float2(c * s.x - sn * (ex * p.x + ey * p.y),
                           c * s.y - sn * (ex * p.y - ey * p.x));
    }
}

__device__ __forceinline__ void apply_bs(float2& s0, float2& s1, int lane, int w,
                                         float th, float ph) {
    float c = cosf(th), sn = sinf(th), c2 = cosf(2.f * th);
    float ex = cosf(ph), ey = sinf(ph);
    int ba = 5 - w, bb = 4 - w;
    float2 p0, p1;
    if (bb >= 1) {
        int lm = ((1 << ba) | (1 << bb)) >> 1;  // lane-bit mask
        p0 = shflxor(s0, lm);
        p1 = shflxor(s1, lm);
    } else { // wires (4,5): bits (1,0): partner = (lane^1, other slot)
        p0 = shflxor(s1, 1);
        p1 = shflxor(s0, 1);
    }
    int n0 = lane * 2, n1 = lane * 2 + 1;
    s0 = bsu(s0, p0, (n0 >> ba) & 1, (n0 >> bb) & 1, c, sn, c2, ex, ey);
    s1 = bsu(s1, p1, (n1 >> ba) & 1, (n1 >> bb) & 1, c, sn, c2, ex, ey);
}

// ---------------- Kernel 1: build U columns (64 blocks x 32 threads) ----------------
__global__ void build_U_kernel(const float* __restrict__ var) {
    int col = blockIdx.x;
    int lane = threadIdx.x;
    float2 s0 = make_float2(0.f, 0.f), s1 = make_float2(0.f, 0.f);
    if (lane * 2 == col) s0.x = 1.f;
    if (lane * 2 + 1 == col) s1.x = 1.f;

    for (int l = 0; l < 2; l++) {
        const float* v = var + 50 * l;
        // BS chain 1: v[0:10]
        for (int i = 0; i < 5; i++)
            apply_bs(s0, s1, lane, i, __ldg(v + 2 * i), __ldg(v + 2 * i + 1));
        // rot: v[10:16]
        for (int w = 0; w < NW; w++) {
            float ph = __ldg(v + 10 + w);
            float sp, cp; sincosf(ph, &sp, &cp);
            apply_diag(s0, s1, lane, w, make_float2(1.f, 0.f), make_float2(cp, sp));
        }
        // squeeze: v[16:22]
        for (int w = 0; w < NW; w++) {
            float r = __ldg(v + 16 + w);
            float sech = 1.f / coshf(r);
            float sr = sqrtf(sech);
            apply_diag(s0, s1, lane, w, make_float2(sr, 0.f), make_float2(sech * sr, 0.f));
        }
        // BS chain 2: v[22:32]
        for (int i = 0; i < 5; i++)
            apply_bs(s0, s1, lane, i, __ldg(v + 22 + 2 * i), __ldg(v + 23 + 2 * i));
        // rot: v[32:38]
        for (int w = 0; w < NW; w++) {
            float ph = __ldg(v + 32 + w);
            float sp, cp; sincosf(ph, &sp, &cp);
            apply_diag(s0, s1, lane, w, make_float2(1.f, 0.f), make_float2(cp, sp));
        }
        // displacement (phi = 0): v[38:44]
        for (int w = 0; w < NW; w++) {
            float r = __ldg(v + 38 + w);
            float pref = expf(-0.5f * r * r);
            apply1(s0, s1, lane, w,
                   make_float2(pref, 0.f), make_float2(-pref * r, 0.f),
                   make_float2(pref * r, 0.f), make_float2(pref * (1.f - r * r), 0.f));
        }
        // Kerr rot: v[44:50]
        for (int w = 0; w < NW; w++) {
            float ph = __ldg(v + 44 + w);
            float sp, cp; sincosf(ph, &sp, &cp);
            apply_diag(s0, s1, lane, w, make_float2(1.f, 0.f), make_float2(cp, sp));
        }
    }
    d_U[(lane * 2) * 64 + col] = s0;
    d_U[(lane * 2 + 1) * 64 + col] = s1;
}

// ---------------- Kernel 2: main (one thread per sample) ----------------
__global__ void __launch_bounds__(256)
ffb_main_kernel(const float* __restrict__ x,
                const float* __restrict__ gamma_, const float* __restrict__ beta_,
                float* __restrict__ out, int nsamp) {
    int s = blockIdx.x * blockDim.x + threadIdx.x;
    if (s >= nsamp) return;
    const float* xr = x + (size_t)s * 64;

    // ---- encoded product-state amplitudes per wire: alpha (real), beta (complex) ----
    float alw[6];
    float2 bew[6];
#pragma unroll
    for (int w = 0; w < 6; w++) {
        float r1   = __ldg(xr + 2 * w);
        float rd   = __ldg(xr + 28 + 2 * w);
        float phid = __ldg(xr + 29 + 2 * w);
        float phik = __ldg(xr + 40 + w);
        float r2   = __ldg(xr + 46 + 2 * w);
        float phir = __ldg(xr + 58 + w);
        float sech1 = 1.f / coshf(r1);
        float sech2 = 1.f / coshf(r2);
        float pref = __expf(-0.5f * rd * rd);
        float c1 = sqrtf(sech1);
        float ss2 = sqrtf(sech2);
        float base = c1 * pref;
        alw[w] = base * ss2;
        float bm = base * rd * sech2 * ss2;
        float th = phid + phik + phir;
        float sth, cth;
        sincosf(th, &sth, &cth);
        bew[w] = make_float2(bm * cth, bm * sth);
    }

    // half-products: p3 over wires 0..2 (index bits 5..3), q3 over wires 3..5 (bits 2..0)
    float2 p3[8], q3[8];
#pragma unroll
    for (int h = 0; h < 8; h++) {
        float2 t = (h & 4) ? bew[0] : make_float2(alw[0], 0.f);
        t = (h & 2) ? cmul(t, bew[1]) : cscale(t, alw[1]);
        p3[h] = (h & 1) ? cmul(t, bew[2]) : cscale(t, alw[2]);
        float2 u = (h & 4) ? bew[3] : make_float2(alw[3], 0.f);
        u = (h & 2) ? cmul(u, bew[4]) : cscale(u, alw[4]);
        q3[h] = (h & 1) ? cmul(u, bew[5]) : cscale(u, alw[5]);
    }

    float sum = 0.f, sumsq = 0.f;
    float* orow = out + (size_t)s * 64;

#pragma unroll
    for (int rb = 0; rb < 4; rb++) {
        float2 acc[16];
#pragma unroll
        for (int r = 0; r < 16; r++) acc[r] = make_float2(0.f, 0.f);

#pragma unroll
        for (int kc = 0; kc < 8; kc++) {
            float2 a[8];
#pragma unroll
            for (int lo = 0; lo < 8; lo++) a[lo] = cmul(p3[kc], q3[lo]);
#pragma unroll
            for (int r = 0; r < 16; r++) {
                const float4* up = (const float4*)&d_U[(rb * 16 + r) * 64 + kc * 8];
#pragma unroll
                for (int q = 0; q < 4; q++) {
                    float4 u = __ldg(up + q);   // (re0, im0, re1, im1) — warp-uniform address
                    float2 a0 = a[2 * q], a1 = a[2 * q + 1];
                    acc[r].x = fmaf(u.x, a0.x, acc[r].x);
                    acc[r].x = fmaf(-u.y, a0.y, acc[r].x);
                    acc[r].y = fmaf(u.x, a0.y, acc[r].y);
                    acc[r].y = fmaf(u.y, a0.x, acc[r].y);
                    acc[r].x = fmaf(u.z, a1.x, acc[r].x);
                    acc[r].x = fmaf(-u.w, a1.y, acc[r].x);
                    acc[r].y = fmaf(u.z, a1.y, acc[r].y);
                    acc[r].y = fmaf(u.w, a1.x, acc[r].y);
                }
            }
        }
        // probs + residual, stash unnormalized, accumulate moments
#pragma unroll
        for (int rq = 0; rq < 4; rq++) {
            float4 xv = __ldg((const float4*)xr + rb * 4 + rq);
            float4 o;
            o.x = acc[rq * 4 + 0].x * acc[rq * 4 + 0].x + acc[rq * 4 + 0].y * acc[rq * 4 + 0].y + xv.x;
            o.y = acc[rq * 4 + 1].x * acc[rq * 4 + 1].x + acc[rq * 4 + 1].y * acc[rq * 4 + 1].y + xv.y;
            o.z = acc[rq * 4 + 2].x * acc[rq * 4 + 2].x + acc[rq * 4 + 2].y * acc[rq * 4 + 2].y + xv.z;
            o.w = acc[rq * 4 + 3].x * acc[rq * 4 + 3].x + acc[rq * 4 + 3].y * acc[rq * 4 + 3].y + xv.w;
            sum += (o.x + o.y) + (o.z + o.w);
            sumsq += o.x * o.x + o.y * o.y + o.z * o.z + o.w * o.w;
            ((float4*)orow)[rb * 4 + rq] = o;
        }
    }

    float mu = sum * (1.f / 64.f);
    float vv = sumsq * (1.f / 64.f) - mu * mu;
    float rstd = rsqrtf(vv + 1e-5f);
#pragma unroll
    for (int g = 0; g < 16; g++) {
        float4 o = ((float4*)orow)[g];        // re-read own store (L1/L2 hit)
        float4 gm = __ldg((const float4*)gamma_ + g);
        float4 bt = __ldg((const float4*)beta_ + g);
        o.x = (o.x - mu) * rstd * gm.x + bt.x;
        o.y = (o.y - mu) * rstd * gm.y + bt.y;
        o.z = (o.z - mu) * rstd * gm.z + bt.z;
        o.w = (o.w - mu) * rstd * gm.w + bt.w;
        ((float4*)orow)[g] = o;
    }
}

// ---------------- launch ----------------
extern "C" void kernel_launch(void* const* d_in, const int* in_sizes, int n_in,
                              void* d_out, int out_size) {
    const float* x     = (const float*)d_in[0];
    const float* var   = (const float*)d_in[1];
    const float* gamma_ = (const float*)d_in[2];
    const float* beta_  = (const float*)d_in[3];
    float* out = (float*)d_out;

    int nsamp = in_sizes[0] / 64;

    build_U_kernel<<<64, 32>>>(var);

    int threads = 256;
    int blocks = (nsamp + threads - 1) / threads;
    ffb_main_kernel<<<blocks, threads>>>(x, gamma_, beta_, out, nsamp);
}